// round 2
// baseline (speedup 1.0000x reference)
#include <cuda_runtime.h>
#include <math.h>

#define BTOT 32768
#define K 64
#define D 64
#define NBLK 256          // main kernel blocks (128 threads each)

// Precomputed per-component data (scratch: __device__ globals, no allocs)
__device__ float d_M[K][D][D];   // lower triangle of A=Linv^T Linv, diag halved, upper zeroed
__device__ float d_bv[K][D];     // b = A mu
__device__ float d_g[K];         // logw_k - halfLogDet_k - 0.5*D*log(2pi) - 0.5*c_k
__device__ float d_partial[NBLK];

// ---------------------------------------------------------------------------
// Prep: per component k (one block of 64 threads):
//   L = tril(pre,-1) + diag(exp(diag(pre))),  pre = scale_raw / 512
//   Linv by forward substitution (thread j owns column j)
//   A = Linv^T Linv ; b = A mu ; c = mu.b ; constants folded into g
// ---------------------------------------------------------------------------
__global__ void prep_kernel(const float* __restrict__ scale_raw,
                            const float* __restrict__ means_raw,
                            const float* __restrict__ weights_raw) {
    const int k = blockIdx.x;
    const int j = threadIdx.x;          // column index, 64 threads

    __shared__ float Ls[D][D];          // L, later overwritten with A
    __shared__ float Vs[D][D + 1];      // Linv (padded)
    __shared__ float ms[D];             // mu
    __shared__ float pdiag[D];          // diag of pre (= log of L diag)
    __shared__ float prodsh[D];         // mu_j * b_j

    const float s2 = 1.0f / 512.0f;    // 1/sqrt(K*D*D)
    const float s1 = 1.0f / 64.0f;     // 1/sqrt(K*D)

    // Load L (thread j handles column j of every row)
    for (int i = 0; i < D; ++i) {
        float p = scale_raw[((size_t)k * D + i) * D + j] * s2;
        float v;
        if (j < i)       v = p;
        else if (j == i) { v = expf(p); pdiag[i] = p; }
        else             v = 0.0f;
        Ls[i][j] = v;
    }
    ms[j] = means_raw[k * D + j] * s1;
    __syncthreads();

    // Invert L (column j). Vs[i][j] for i >= j; zero above (written for safety)
    for (int i = 0; i < j; ++i) Vs[i][j] = 0.0f;
    Vs[j][j] = 1.0f / Ls[j][j];
    for (int i = j + 1; i < D; ++i) {
        float s = 0.0f;
        for (int m = j; m < i; ++m) s += Ls[i][m] * Vs[m][j];
        Vs[i][j] = -s / Ls[i][i];
    }
    __syncthreads();

    // A[p][j] = sum_{i>=max(p,j)} Vs[i][p] * Vs[i][j]   (overwrite Ls with A)
    for (int p = 0; p < D; ++p) {
        int lo = (p > j) ? p : j;
        float a = 0.0f;
        for (int i = lo; i < D; ++i) a += Vs[i][p] * Vs[i][j];
        Ls[p][j] = a;
    }
    __syncthreads();

    // b[j] = sum_q A[j][q] * mu[q]  (row j of symmetric A)
    float bj = 0.0f;
    for (int q = 0; q < D; ++q) bj += Ls[j][q] * ms[q];
    d_bv[k][j] = bj;
    prodsh[j] = ms[j] * bj;

    // Store M row j: strict lower = A, diag halved, upper zero
    for (int q = 0; q < D; ++q) {
        float a = Ls[j][q];
        float v = (q < j) ? a : ((q == j) ? 0.5f * a : 0.0f);
        d_M[k][j][q] = v;
    }
    __syncthreads();

    if (j == 0) {
        float hld = 0.0f, c = 0.0f;
        for (int i = 0; i < D; ++i) { hld += pdiag[i]; c += prodsh[i]; }
        // log-softmax of weights (K values, done redundantly per block — cheap)
        const float s3 = 0.125f;   // 1/sqrt(K)
        float wmax = -1e30f;
        for (int q = 0; q < K; ++q) {
            float wq = weights_raw[q] * s3;
            wmax = fmaxf(wmax, wq);
        }
        float lse = 0.0f;
        for (int q = 0; q < K; ++q) lse += expf(weights_raw[q] * s3 - wmax);
        float logwk = weights_raw[k] * s3 - (wmax + logf(lse));
        const float HALF_D_LOG2PI = 0.5f * 64.0f * 1.8378770664093453f;
        d_g[k] = logwk - hld - HALF_D_LOG2PI - 0.5f * c;
    }
}

// ---------------------------------------------------------------------------
// Main: one thread per sample. val_bk = -x^T M x (x2 implicit) + b.x + g
// online logsumexp over k, then block-sum of lp.
// ---------------------------------------------------------------------------
__global__ __launch_bounds__(128) void gmm_main(const float* __restrict__ x) {
    __shared__ float4 Ms[D * D / 4];   // 16 KB: component matrix M (float4 rows)
    __shared__ float  bs[D];
    __shared__ float  gsh;
    __shared__ float  red[128];

    const int tid = threadIdx.x;
    const int b = blockIdx.x * 128 + tid;

    // sample row into registers
    float xr[D];
    const float4* xp = (const float4*)(x + (size_t)b * D);
    #pragma unroll
    for (int i = 0; i < D / 4; ++i) {
        float4 v = xp[i];
        xr[4 * i + 0] = v.x; xr[4 * i + 1] = v.y;
        xr[4 * i + 2] = v.z; xr[4 * i + 3] = v.w;
    }

    float mmax = -1e30f;
    float ssum = 0.0f;

    for (int k = 0; k < K; ++k) {
        __syncthreads();
        // cooperative load of M_k (1024 float4), b_k, g_k
        const float4* Mg = (const float4*)&d_M[k][0][0];
        #pragma unroll
        for (int r = 0; r < 8; ++r) Ms[tid + 128 * r] = Mg[tid + 128 * r];
        if (tid < 16) ((float4*)bs)[tid] = ((const float4*)&d_bv[k][0])[tid];
        if (tid == 127) gsh = d_g[k];
        __syncthreads();

        // quad = x^T M x over lower triangle (rows padded to float4 boundary;
        // padding entries are exact zeros in d_M)
        float quad = 0.0f;
        #pragma unroll
        for (int i = 0; i < D; ++i) {
            const int nj4 = (i >> 2) + 1;        // float4 chunks covering j<=i
            float r = 0.0f;
            #pragma unroll
            for (int j4 = 0; j4 < nj4; ++j4) {
                float4 mv = Ms[i * 16 + j4];
                r = fmaf(mv.x, xr[4 * j4 + 0], r);
                r = fmaf(mv.y, xr[4 * j4 + 1], r);
                r = fmaf(mv.z, xr[4 * j4 + 2], r);
                r = fmaf(mv.w, xr[4 * j4 + 3], r);
            }
            quad = fmaf(xr[i], r, quad);
        }
        float dot = 0.0f;
        #pragma unroll
        for (int i = 0; i < D; ++i) dot = fmaf(bs[i], xr[i], dot);

        float val = dot - quad + gsh;  // comp_lp + logw  (maha = 2*quad)

        // online logsumexp
        if (val > mmax) {
            ssum = ssum * expf(mmax - val) + 1.0f;
            mmax = val;
        } else {
            ssum += expf(val - mmax);
        }
    }

    float lp = mmax + logf(ssum);

    // deterministic block reduction
    red[tid] = lp;
    __syncthreads();
    #pragma unroll
    for (int s = 64; s > 0; s >>= 1) {
        if (tid < s) red[tid] += red[tid + s];
        __syncthreads();
    }
    if (tid == 0) d_partial[blockIdx.x] = red[0];
}

__global__ void finish_kernel(float* __restrict__ out) {
    __shared__ float red[NBLK];
    int tid = threadIdx.x;
    red[tid] = d_partial[tid];
    __syncthreads();
    #pragma unroll
    for (int s = NBLK / 2; s > 0; s >>= 1) {
        if (tid < s) red[tid] += red[tid + s];
        __syncthreads();
    }
    if (tid == 0) out[0] = -red[0] / (float)BTOT;
}

extern "C" void kernel_launch(void* const* d_in, const int* in_sizes, int n_in,
                              void* d_out, int out_size) {
    const float* x      = (const float*)d_in[0];
    const float* means  = (const float*)d_in[1];
    const float* scale  = (const float*)d_in[2];
    const float* wraw   = (const float*)d_in[3];

    prep_kernel<<<K, D>>>(scale, means, wraw);
    gmm_main<<<NBLK, 128>>>(x);
    finish_kernel<<<1, NBLK>>>((float*)d_out);
}

// round 3
// speedup vs baseline: 1.0578x; 1.0578x over previous
#include <cuda_runtime.h>
#include <math.h>

#define BTOT 32768
#define K 64
#define D 64
#define NBLK 256          // main kernel blocks (128 threads each)

// Precomputed per-component data (scratch: __device__ globals, no allocs)
__device__ float d_M[K][D][D];   // lower triangle of A=Linv^T Linv, diag halved, upper zeroed
__device__ float d_bv[K][D];     // b = A mu
__device__ float d_g[K];         // logw_k - halfLogDet_k - 0.5*D*log(2pi) - 0.5*c_k
__device__ float d_partial[NBLK];

// ---------------------------------------------------------------------------
// Prep: per component k (one block of 64 threads):
//   L = tril(pre,-1) + diag(exp(diag(pre))),  pre = scale_raw / 512
//   Linv by forward substitution (thread j owns column j)
//   A = Linv^T Linv ; b = A mu ; c = mu.b ; constants folded into g
// ---------------------------------------------------------------------------
__global__ void prep_kernel(const float* __restrict__ scale_raw,
                            const float* __restrict__ means_raw,
                            const float* __restrict__ weights_raw) {
    const int k = blockIdx.x;
    const int j = threadIdx.x;          // column index, 64 threads

    __shared__ float Ls[D][D];          // L, later overwritten with A
    __shared__ float Vs[D][D + 1];      // Linv (padded)
    __shared__ float ms[D];             // mu
    __shared__ float pdiag[D];          // diag of pre (= log of L diag)
    __shared__ float prodsh[D];         // mu_j * b_j

    const float s2 = 1.0f / 512.0f;    // 1/sqrt(K*D*D)
    const float s1 = 1.0f / 64.0f;     // 1/sqrt(K*D)

    // Load L (thread j handles column j of every row)
    for (int i = 0; i < D; ++i) {
        float p = scale_raw[((size_t)k * D + i) * D + j] * s2;
        float v;
        if (j < i)       v = p;
        else if (j == i) { v = expf(p); pdiag[i] = p; }
        else             v = 0.0f;
        Ls[i][j] = v;
    }
    ms[j] = means_raw[k * D + j] * s1;
    __syncthreads();

    // Invert L (column j). Vs[i][j] for i >= j; zero above (written for safety)
    for (int i = 0; i < j; ++i) Vs[i][j] = 0.0f;
    Vs[j][j] = 1.0f / Ls[j][j];
    for (int i = j + 1; i < D; ++i) {
        float s = 0.0f;
        for (int m = j; m < i; ++m) s += Ls[i][m] * Vs[m][j];
        Vs[i][j] = -s / Ls[i][i];
    }
    __syncthreads();

    // A[p][j] = sum_{i>=max(p,j)} Vs[i][p] * Vs[i][j]   (overwrite Ls with A)
    for (int p = 0; p < D; ++p) {
        int lo = (p > j) ? p : j;
        float a = 0.0f;
        for (int i = lo; i < D; ++i) a += Vs[i][p] * Vs[i][j];
        Ls[p][j] = a;
    }
    __syncthreads();

    // b[j] = sum_q A[j][q] * mu[q]  (row j of symmetric A)
    float bj = 0.0f;
    for (int q = 0; q < D; ++q) bj += Ls[j][q] * ms[q];
    d_bv[k][j] = bj;
    prodsh[j] = ms[j] * bj;

    // Store M row j: strict lower = A, diag halved, upper zero
    for (int q = 0; q < D; ++q) {
        float a = Ls[j][q];
        float v = (q < j) ? a : ((q == j) ? 0.5f * a : 0.0f);
        d_M[k][j][q] = v;
    }
    __syncthreads();

    if (j == 0) {
        float hld = 0.0f, c = 0.0f;
        for (int i = 0; i < D; ++i) { hld += pdiag[i]; c += prodsh[i]; }
        // log-softmax of weights (K values, done redundantly per block — cheap)
        const float s3 = 0.125f;   // 1/sqrt(K)
        float wmax = -1e30f;
        for (int q = 0; q < K; ++q) {
            float wq = weights_raw[q] * s3;
            wmax = fmaxf(wmax, wq);
        }
        float lse = 0.0f;
        for (int q = 0; q < K; ++q) lse += expf(weights_raw[q] * s3 - wmax);
        float logwk = weights_raw[k] * s3 - (wmax + logf(lse));
        const float HALF_D_LOG2PI = 0.5f * 64.0f * 1.8378770664093453f;
        d_g[k] = logwk - hld - HALF_D_LOG2PI - 0.5f * c;
    }
}

// ---------------------------------------------------------------------------
// Main: one thread per sample. val_bk = -x^T M x (x2 implicit) + b.x + g
// online logsumexp over k, then block-sum of lp.
// ---------------------------------------------------------------------------
__global__ __launch_bounds__(128) void gmm_main(const float* __restrict__ x) {
    __shared__ float4 Ms[D * D / 4];   // 16 KB: component matrix M (float4 rows)
    __shared__ float  bs[D];
    __shared__ float  gsh;
    __shared__ float  red[128];

    const int tid = threadIdx.x;
    const int b = blockIdx.x * 128 + tid;

    // sample row into registers
    float xr[D];
    const float4* xp = (const float4*)(x + (size_t)b * D);
    #pragma unroll
    for (int i = 0; i < D / 4; ++i) {
        float4 v = xp[i];
        xr[4 * i + 0] = v.x; xr[4 * i + 1] = v.y;
        xr[4 * i + 2] = v.z; xr[4 * i + 3] = v.w;
    }

    float mmax = -1e30f;
    float ssum = 0.0f;

    for (int k = 0; k < K; ++k) {
        __syncthreads();
        // cooperative load of M_k (1024 float4), b_k, g_k
        const float4* Mg = (const float4*)&d_M[k][0][0];
        #pragma unroll
        for (int r = 0; r < 8; ++r) Ms[tid + 128 * r] = Mg[tid + 128 * r];
        if (tid < 16) ((float4*)bs)[tid] = ((const float4*)&d_bv[k][0])[tid];
        if (tid == 127) gsh = d_g[k];
        __syncthreads();

        // quad = x^T M x over lower triangle (rows padded to float4 boundary;
        // padding entries are exact zeros in d_M)
        float quad = 0.0f;
        #pragma unroll
        for (int i = 0; i < D; ++i) {
            const int nj4 = (i >> 2) + 1;        // float4 chunks covering j<=i
            float r = 0.0f;
            #pragma unroll
            for (int j4 = 0; j4 < nj4; ++j4) {
                float4 mv = Ms[i * 16 + j4];
                r = fmaf(mv.x, xr[4 * j4 + 0], r);
                r = fmaf(mv.y, xr[4 * j4 + 1], r);
                r = fmaf(mv.z, xr[4 * j4 + 2], r);
                r = fmaf(mv.w, xr[4 * j4 + 3], r);
            }
            quad = fmaf(xr[i], r, quad);
        }
        float dot = 0.0f;
        #pragma unroll
        for (int i = 0; i < D; ++i) dot = fmaf(bs[i], xr[i], dot);

        float val = dot - quad + gsh;  // comp_lp + logw  (maha = 2*quad)

        // online logsumexp
        if (val > mmax) {
            ssum = ssum * expf(mmax - val) + 1.0f;
            mmax = val;
        } else {
            ssum += expf(val - mmax);
        }
    }

    float lp = mmax + logf(ssum);

    // deterministic block reduction
    red[tid] = lp;
    __syncthreads();
    #pragma unroll
    for (int s = 64; s > 0; s >>= 1) {
        if (tid < s) red[tid] += red[tid + s];
        __syncthreads();
    }
    if (tid == 0) d_partial[blockIdx.x] = red[0];
}

__global__ void finish_kernel(float* __restrict__ out) {
    __shared__ float red[NBLK];
    int tid = threadIdx.x;
    red[tid] = d_partial[tid];
    __syncthreads();
    #pragma unroll
    for (int s = NBLK / 2; s > 0; s >>= 1) {
        if (tid < s) red[tid] += red[tid + s];
        __syncthreads();
    }
    if (tid == 0) out[0] = -red[0] / (float)BTOT;
}

extern "C" void kernel_launch(void* const* d_in, const int* in_sizes, int n_in,
                              void* d_out, int out_size) {
    const float* x      = (const float*)d_in[0];
    const float* means  = (const float*)d_in[1];
    const float* scale  = (const float*)d_in[2];
    const float* wraw   = (const float*)d_in[3];

    prep_kernel<<<K, D>>>(scale, means, wraw);
    gmm_main<<<NBLK, 128>>>(x);
    finish_kernel<<<1, NBLK>>>((float*)d_out);
}

// round 4
// speedup vs baseline: 1.5002x; 1.4182x over previous
#include <cuda_runtime.h>
#include <math.h>

#define BTOT 32768
#define K 64
#define D 64
#define NBLK 256          // main kernel blocks (128 threads each)

typedef unsigned long long ull;

// Precomputed per-component data (scratch: __device__ globals, no allocs)
__device__ float d_M[K][D][D];   // lower triangle of A=Linv^T Linv, diag halved, upper zeroed
__device__ float d_bv[K][D];     // b = A mu
__device__ float d_g[K];         // logw_k - halfLogDet_k - 0.5*D*log(2pi) - 0.5*c_k
__device__ float d_partial[NBLK];

// ---------------- packed f32x2 helpers ----------------
__device__ __forceinline__ ull fma2(ull a, ull b, ull c) {
    ull d;
    asm("fma.rn.f32x2 %0, %1, %2, %3;" : "=l"(d) : "l"(a), "l"(b), "l"(c));
    return d;
}
__device__ __forceinline__ float hadd2(ull a) {
    float lo, hi;
    asm("mov.b64 {%0, %1}, %2;" : "=f"(lo), "=f"(hi) : "l"(a));
    return lo + hi;
}
__device__ __forceinline__ ull pack2(float lo, float hi) {
    ull d;
    asm("mov.b64 %0, {%1, %2};" : "=l"(d) : "f"(lo), "f"(hi));
    return d;
}
__device__ __forceinline__ void lds2(ull& a, ull& b, unsigned addr) {
    asm("ld.shared.v2.b64 {%0, %1}, [%2];" : "=l"(a), "=l"(b) : "r"(addr));
}

// ---------------------------------------------------------------------------
// Prep: per component k (one block of 64 threads):
//   L = tril(pre,-1) + diag(exp(diag(pre))),  pre = scale_raw / 512
//   Row-sweep forward substitution for Linv (uniform trip counts, 4-way ILP),
//   A = Linv^T Linv ; b = A mu ; constants folded into g.
// ---------------------------------------------------------------------------
__global__ void prep_kernel(const float* __restrict__ scale_raw,
                            const float* __restrict__ means_raw,
                            const float* __restrict__ weights_raw) {
    const int k = blockIdx.x;
    const int j = threadIdx.x;          // 64 threads

    __shared__ float Ls[D][D + 1];      // L, later overwritten with A
    __shared__ float Vs[D][D + 1];      // Linv
    __shared__ float rdiag[D];
    __shared__ float ms[D];
    __shared__ float pdiag[D];
    __shared__ float prodsh[D];

    const float sc2 = 1.0f / 512.0f;    // 1/sqrt(K*D*D)
    const float sc1 = 1.0f / 64.0f;     // 1/sqrt(K*D)

    // Load L (thread j handles column j of every row; coalesced over j)
    for (int i = 0; i < D; ++i) {
        float p = scale_raw[((size_t)k * D + i) * D + j] * sc2;
        float v;
        if (j < i)       v = p;
        else if (j == i) { v = expf(p); pdiag[i] = p; rdiag[i] = 1.0f / v; }
        else             v = 0.0f;
        Ls[i][j] = v;
    }
    ms[j] = means_raw[k * D + j] * sc1;
    __syncthreads();

    // Row-sweep inversion: V[i][j] = (delta_ij - sum_{m<i} L[i][m] V[m][j]) / L[i][i]
    // (for i<j the sum is over zeros, giving exactly 0)
    for (int i = 0; i < D; ++i) {
        float a0 = 0.f, a1 = 0.f, a2 = 0.f, a3 = 0.f;
        int m = 0;
        for (; m + 4 <= i; m += 4) {
            a0 = fmaf(Ls[i][m + 0], Vs[m + 0][j], a0);
            a1 = fmaf(Ls[i][m + 1], Vs[m + 1][j], a1);
            a2 = fmaf(Ls[i][m + 2], Vs[m + 2][j], a2);
            a3 = fmaf(Ls[i][m + 3], Vs[m + 3][j], a3);
        }
        for (; m < i; ++m) a0 = fmaf(Ls[i][m], Vs[m][j], a0);
        float s = (a0 + a1) + (a2 + a3);
        float v = (((i == j) ? 1.0f : 0.0f) - s) * rdiag[i];
        Vs[i][j] = (i >= j) ? v : 0.0f;
        __syncthreads();
    }

    // A[p][j] = sum_i Vs[i][p]*Vs[i][j]; start aligned below max(p,j) — the
    // extra terms multiply exact zeros. Overwrite Ls with A.
    for (int p = 0; p < D; ++p) {
        int lo = ((p > j) ? p : j) & ~3;
        float a0 = 0.f, a1 = 0.f, a2 = 0.f, a3 = 0.f;
        for (int i = lo; i < D; i += 4) {
            a0 = fmaf(Vs[i + 0][p], Vs[i + 0][j], a0);
            a1 = fmaf(Vs[i + 1][p], Vs[i + 1][j], a1);
            a2 = fmaf(Vs[i + 2][p], Vs[i + 2][j], a2);
            a3 = fmaf(Vs[i + 3][p], Vs[i + 3][j], a3);
        }
        Ls[p][j] = (a0 + a1) + (a2 + a3);
    }
    __syncthreads();

    // b[j] = row j of symmetric A dot mu
    {
        float a0 = 0.f, a1 = 0.f, a2 = 0.f, a3 = 0.f;
        for (int q = 0; q < D; q += 4) {
            a0 = fmaf(Ls[j][q + 0], ms[q + 0], a0);
            a1 = fmaf(Ls[j][q + 1], ms[q + 1], a1);
            a2 = fmaf(Ls[j][q + 2], ms[q + 2], a2);
            a3 = fmaf(Ls[j][q + 3], ms[q + 3], a3);
        }
        float bj = (a0 + a1) + (a2 + a3);
        d_bv[k][j] = bj;
        prodsh[j] = ms[j] * bj;
    }

    // Store M row j: strict lower = A, diag halved, upper zero
    for (int q = 0; q < D; ++q) {
        float a = Ls[j][q];
        d_M[k][j][q] = (q < j) ? a : ((q == j) ? 0.5f * a : 0.0f);
    }
    __syncthreads();

    if (j == 0) {
        float hld = 0.0f, c = 0.0f;
        for (int i = 0; i < D; ++i) { hld += pdiag[i]; c += prodsh[i]; }
        const float s3 = 0.125f;   // 1/sqrt(K)
        float wmax = -1e30f;
        for (int q = 0; q < K; ++q) wmax = fmaxf(wmax, weights_raw[q] * s3);
        float lse = 0.0f;
        for (int q = 0; q < K; ++q) lse += expf(weights_raw[q] * s3 - wmax);
        float logwk = weights_raw[k] * s3 - (wmax + logf(lse));
        const float HALF_D_LOG2PI = 0.5f * 64.0f * 1.8378770664093453f;
        d_g[k] = logwk - hld - HALF_D_LOG2PI - 0.5f * c;
    }
}

// ---------------------------------------------------------------------------
// Main: one thread per sample. val_bk = b.x - x^T M x + g  (maha = 2*quad)
// Packed f32x2 FMAs throughout; double-buffered component tiles.
// ---------------------------------------------------------------------------
__global__ __launch_bounds__(128) void gmm_main(const float* __restrict__ x) {
    __shared__ float4 Ms[2][D * D / 4];   // 2 x 16 KB
    __shared__ float4 Bsh[2][D / 4];
    __shared__ float  gsh[2];
    __shared__ float  red[128];

    const int tid = threadIdx.x;
    const size_t b = (size_t)blockIdx.x * 128 + tid;

    // sample row, packed into f32x2 pairs
    ull xp2[32];
    const float4* xp = (const float4*)(x + b * D);
    #pragma unroll
    for (int i = 0; i < 16; ++i) {
        float4 v = xp[i];
        xp2[2 * i + 0] = pack2(v.x, v.y);
        xp2[2 * i + 1] = pack2(v.z, v.w);
    }

    // preload k = 0 tile
    {
        const float4* Mg = (const float4*)&d_M[0][0][0];
        #pragma unroll
        for (int r = 0; r < 8; ++r) Ms[0][tid + 128 * r] = Mg[tid + 128 * r];
        if (tid < 16) Bsh[0][tid] = ((const float4*)&d_bv[0][0])[tid];
        if (tid == 0) gsh[0] = d_g[0];
    }
    __syncthreads();

    float mmax = -1e30f;
    float ssum = 0.0f;

    for (int k = 0; k < K; ++k) {
        const int cur = k & 1, nxt = cur ^ 1;

        // prefetch next component into registers (hidden under compute)
        float4 pf[8]; float4 pb; float pg = 0.0f;
        {
            const int kn = (k + 1 < K) ? k + 1 : K - 1;
            const float4* Mg = (const float4*)&d_M[kn][0][0];
            #pragma unroll
            for (int r = 0; r < 8; ++r) pf[r] = Mg[tid + 128 * r];
            if (tid < 16) pb = ((const float4*)&d_bv[kn][0])[tid];
            if (tid == 0) pg = d_g[kn];
        }

        const unsigned mbase = (unsigned)__cvta_generic_to_shared(&Ms[cur][0]);
        const unsigned bbase = (unsigned)__cvta_generic_to_shared(&Bsh[cur][0]);

        ull qacc = 0ULL;   // packed quad accumulator
        ull bacc = 0ULL;   // packed b-dot accumulator

        // rows 4t..4t+3 all need exactly t+1 float4 chunks (padding is exact 0)
        #pragma unroll
        for (int t = 0; t < 16; ++t) {
            ull a0 = 0ULL, a1 = 0ULL, a2 = 0ULL, a3 = 0ULL;
            const unsigned ra = mbase + (unsigned)t * 1024u;   // row 4t (256 B/row)
            #pragma unroll
            for (int c = 0; c <= t; ++c) {
                ull m0a, m0b, m1a, m1b, m2a, m2b, m3a, m3b;
                lds2(m0a, m0b, ra + 16u * c);
                lds2(m1a, m1b, ra + 256u + 16u * c);
                lds2(m2a, m2b, ra + 512u + 16u * c);
                lds2(m3a, m3b, ra + 768u + 16u * c);
                const ull xlo = xp2[2 * c], xhi = xp2[2 * c + 1];
                a0 = fma2(m0a, xlo, a0); a0 = fma2(m0b, xhi, a0);
                a1 = fma2(m1a, xlo, a1); a1 = fma2(m1b, xhi, a1);
                a2 = fma2(m2a, xlo, a2); a2 = fma2(m2b, xhi, a2);
                a3 = fma2(m3a, xlo, a3); a3 = fma2(m3b, xhi, a3);
            }
            // quad += x_{4t}*s0 + x_{4t+1}*s1 + x_{4t+2}*s2 + x_{4t+3}*s3
            qacc = fma2(xp2[2 * t + 0], pack2(hadd2(a0), hadd2(a1)), qacc);
            qacc = fma2(xp2[2 * t + 1], pack2(hadd2(a2), hadd2(a3)), qacc);
            // b-dot for the same 4 columns
            ull b01, b23;
            lds2(b01, b23, bbase + 16u * t);
            bacc = fma2(b01, xp2[2 * t + 0], bacc);
            bacc = fma2(b23, xp2[2 * t + 1], bacc);
        }

        const float val = hadd2(bacc) - hadd2(qacc) + gsh[cur];

        // online logsumexp
        if (val > mmax) {
            ssum = ssum * expf(mmax - val) + 1.0f;
            mmax = val;
        } else {
            ssum += expf(val - mmax);
        }

        // stage prefetched tile into the other buffer
        #pragma unroll
        for (int r = 0; r < 8; ++r) Ms[nxt][tid + 128 * r] = pf[r];
        if (tid < 16) Bsh[nxt][tid] = pb;
        if (tid == 0) gsh[nxt] = pg;
        __syncthreads();
    }

    float lp = mmax + logf(ssum);

    // deterministic block reduction
    red[tid] = lp;
    __syncthreads();
    #pragma unroll
    for (int s = 64; s > 0; s >>= 1) {
        if (tid < s) red[tid] += red[tid + s];
        __syncthreads();
    }
    if (tid == 0) d_partial[blockIdx.x] = red[0];
}

__global__ void finish_kernel(float* __restrict__ out) {
    __shared__ float red[NBLK];
    int tid = threadIdx.x;
    red[tid] = d_partial[tid];
    __syncthreads();
    #pragma unroll
    for (int s = NBLK / 2; s > 0; s >>= 1) {
        if (tid < s) red[tid] += red[tid + s];
        __syncthreads();
    }
    if (tid == 0) out[0] = -red[0] / (float)BTOT;
}

extern "C" void kernel_launch(void* const* d_in, const int* in_sizes, int n_in,
                              void* d_out, int out_size) {
    const float* x      = (const float*)d_in[0];
    const float* means  = (const float*)d_in[1];
    const float* scale  = (const float*)d_in[2];
    const float* wraw   = (const float*)d_in[3];

    prep_kernel<<<K, D>>>(scale, means, wraw);
    gmm_main<<<NBLK, 128>>>(x);
    finish_kernel<<<1, NBLK>>>((float*)d_out);
}